// round 8
// baseline (speedup 1.0000x reference)
#include <cuda_runtime.h>
#include <math.h>

#define BATCH 2
#define SEQ   1024
#define DIMC  256
#define HEADS 4
#define DH    64
#define INNER 256
#define MTOK  (BATCH*SEQ)   // 2048
#define DEPTH 4

#define ACT_CAP ((size_t)MTOK*DIMC)                 // 524288
#define SCR_CAP ((size_t)BATCH*HEADS*SEQ*SEQ)       // 8388608

// ---------------- scratch (device globals) ----------------
__device__ float g_x_re[ACT_CAP],  g_x_im[ACT_CAP];
__device__ float g_xn_re[ACT_CAP], g_xn_im[ACT_CAP];
__device__ float g_w_re[ACT_CAP],  g_w_im[ACT_CAP];
__device__ float g_att_re[ACT_CAP],g_att_im[ACT_CAP];
__device__ float g_gx_re[ACT_CAP], g_gx_im[ACT_CAP];
__device__ float g_d_re[SCR_CAP];
__device__ float g_d_im[SCR_CAP];

__device__ __forceinline__ float* gbuf(int id, int comp) {
    switch (id) {
        case 0: return comp ? g_x_im   : g_x_re;
        case 1: return comp ? g_xn_im  : g_xn_re;
        case 2: return comp ? g_w_im   : g_w_re;
        case 3: return comp ? g_att_im : g_att_re;
        default:return comp ? g_gx_im  : g_gx_re;
    }
}

// ---------------- input copy ----------------
__global__ void init_x_kernel(const float* __restrict__ a, const float* __restrict__ b, int n)
{
    int i = blockIdx.x*blockDim.x + threadIdx.x;
    if (i < n) { g_x_re[i] = a[i]; g_x_im[i] = b[i]; }
}

// ---------------- output pack: REAL PART ONLY (float32 lowering drops imag) ----------------
__global__ void pack_out_kernel(float* __restrict__ out, int n)
{
    int i = blockIdx.x*blockDim.x + threadIdx.x;
    if (i < n) out[i] = g_x_re[i];
}

// ---------------- complex layernorm ----------------
__global__ void ln_kernel(int srcid,
                          const float* __restrict__ wr, const float* __restrict__ wi,
                          const float* __restrict__ br, const float* __restrict__ bi)
{
    const float* xr = gbuf(srcid, 0);
    const float* xi = gbuf(srcid, 1);
    float* yr = gbuf(1, 0);
    float* yi = gbuf(1, 1);

    int tok = blockIdx.x;
    int t   = threadIdx.x;           // 256 threads == DIMC
    size_t xidx = (size_t)tok*DIMC + t;
    float vr = xr[xidx];
    float vi = xi[xidx];

    float s0 = vr, s1 = vi, s2 = vr*vr, s3 = vi*vi;
    #pragma unroll
    for (int o = 16; o > 0; o >>= 1) {
        s0 += __shfl_xor_sync(0xffffffffu, s0, o);
        s1 += __shfl_xor_sync(0xffffffffu, s1, o);
        s2 += __shfl_xor_sync(0xffffffffu, s2, o);
        s3 += __shfl_xor_sync(0xffffffffu, s3, o);
    }
    __shared__ float sh0[8], sh1[8], sh2[8], sh3[8];
    int warp = t >> 5;
    if ((t & 31) == 0) { sh0[warp]=s0; sh1[warp]=s1; sh2[warp]=s2; sh3[warp]=s3; }
    __syncthreads();
    float t0=0.f, t1=0.f, t2=0.f, t3=0.f;
    #pragma unroll
    for (int i = 0; i < 8; i++) { t0+=sh0[i]; t1+=sh1[i]; t2+=sh2[i]; t3+=sh3[i]; }

    const float inv = 1.0f / DIMC;
    float mr = t0*inv, mi = t1*inv;
    float var_r = t2*inv - mr*mr;
    float var_i = t3*inv - mi*mi;
    // principal complex sqrt of (var_r + eps) + i var_i
    float a = var_r + 1e-5f, b = var_i;
    float r = sqrtf(a*a + b*b);
    float sre = sqrtf(fmaxf(0.5f*(r + a), 0.f));
    float sim = sqrtf(fmaxf(0.5f*(r - a), 0.f));
    if (b < 0.f) sim = -sim;
    float invr = 1.0f / fmaxf(r, 1e-30f);   // |sqrt|^2 == r
    float dxr = vr - mr, dxi = vi - mi;
    float xnr = (dxr*sre + dxi*sim) * invr;
    float xni = (dxi*sre - dxr*sim) * invr;
    float Wr = wr[t], Wi = wi[t];
    yr[xidx] = Wr*xnr - Wi*xni + br[t];
    yi[xidx] = Wr*xni + Wi*xnr + bi[t];
}

// ---------------- complex GEMM: Y = X @ W^T (+ epilogue) ----------------
// MODE 0: plain   MODE 1: +bias[col]+residual   MODE 2: CReLU(res + 0.1*y - 0.01_real)
template <int MODE>
__global__ void gemm_xwt(int xid,
                         const float* __restrict__ Wr, const float* __restrict__ Wi,
                         int yid, int K, int ldx, int ldw, int ldy,
                         const float* __restrict__ br, const float* __restrict__ bi,
                         int rid)
{
    const float* Xr = gbuf(xid, 0);
    const float* Xi = gbuf(xid, 1);
    float* Yr = gbuf(yid, 0);
    float* Yi = gbuf(yid, 1);

    __shared__ float As_r[32][33], As_i[32][33], Bs_r[32][33], Bs_i[32][33];
    int tx = threadIdx.x, ty = threadIdx.y;      // 16x16
    int row0 = blockIdx.y*32, col0 = blockIdx.x*32;
    float ar00=0,ai00=0, ar01=0,ai01=0, ar10=0,ai10=0, ar11=0,ai11=0;

    for (int kt = 0; kt < K; kt += 32) {
        #pragma unroll
        for (int j = 0; j < 2; j++) {
            int rrow = ty + 16*j;
            #pragma unroll
            for (int i = 0; i < 2; i++) {
                int c = tx + 16*i;
                As_r[rrow][c] = Xr[(size_t)(row0+rrow)*ldx + kt + c];
                As_i[rrow][c] = Xi[(size_t)(row0+rrow)*ldx + kt + c];
                Bs_r[rrow][c] = Wr[(size_t)(col0+rrow)*ldw + kt + c];
                Bs_i[rrow][c] = Wi[(size_t)(col0+rrow)*ldw + kt + c];
            }
        }
        __syncthreads();
        #pragma unroll
        for (int kk = 0; kk < 32; kk++) {
            float xr0 = As_r[ty][kk],    xi0 = As_i[ty][kk];
            float xr1 = As_r[ty+16][kk], xi1 = As_i[ty+16][kk];
            float wr0 = Bs_r[tx][kk],    wi0 = Bs_i[tx][kk];
            float wr1 = Bs_r[tx+16][kk], wi1 = Bs_i[tx+16][kk];
            ar00 += xr0*wr0 - xi0*wi0;  ai00 += xr0*wi0 + xi0*wr0;
            ar01 += xr0*wr1 - xi0*wi1;  ai01 += xr0*wi1 + xi0*wr1;
            ar10 += xr1*wr0 - xi1*wi0;  ai10 += xr1*wi0 + xi1*wr0;
            ar11 += xr1*wr1 - xi1*wi1;  ai11 += xr1*wi1 + xi1*wr1;
        }
        __syncthreads();
    }

    const float* rr = gbuf(rid, 0);
    const float* ri = gbuf(rid, 1);
    float accr[2][2] = {{ar00, ar01},{ar10, ar11}};
    float acci[2][2] = {{ai00, ai01},{ai10, ai11}};
    #pragma unroll
    for (int j = 0; j < 2; j++) {
        int row = row0 + ty + 16*j;
        #pragma unroll
        for (int i = 0; i < 2; i++) {
            int col = col0 + tx + 16*i;
            size_t oi = (size_t)row*ldy + col;
            float yr = accr[j][i], yi2 = acci[j][i];
            if (MODE == 0) {
                Yr[oi] = yr;  Yi[oi] = yi2;
            } else if (MODE == 1) {
                Yr[oi] = yr + br[col] + rr[oi];
                Yi[oi] = yi2 + bi[col] + ri[oi];
            } else {
                float zr = rr[oi] + 0.1f*yr - 0.01f;
                float zi = ri[oi] + 0.1f*yi2;
                Yr[oi] = fmaxf(zr, 0.f);
                Yi[oi] = fmaxf(zi, 0.f);
            }
        }
    }
}

// ---------------- dots: D = scale * W W^H per (b,h) ----------------
__global__ void dots_kernel()
{
    int bh = blockIdx.z;
    int b = bh >> 2, h = bh & 3;
    const float* Ar = g_w_re + (size_t)b*SEQ*INNER + h*DH;
    const float* Ai = g_w_im + (size_t)b*SEQ*INNER + h*DH;
    __shared__ float Qs_r[32][33], Qs_i[32][33], Ks_r[32][33], Ks_i[32][33];
    int tx = threadIdx.x, ty = threadIdx.y;
    int row0 = blockIdx.y*32, col0 = blockIdx.x*32;
    float ar00=0,ai00=0, ar01=0,ai01=0, ar10=0,ai10=0, ar11=0,ai11=0;

    #pragma unroll
    for (int kt = 0; kt < DH; kt += 32) {
        #pragma unroll
        for (int j = 0; j < 2; j++) {
            int rrow = ty + 16*j;
            #pragma unroll
            for (int i = 0; i < 2; i++) {
                int c = tx + 16*i;
                Qs_r[rrow][c] = Ar[(size_t)(row0+rrow)*INNER + kt + c];
                Qs_i[rrow][c] = Ai[(size_t)(row0+rrow)*INNER + kt + c];
                Ks_r[rrow][c] = Ar[(size_t)(col0+rrow)*INNER + kt + c];
                Ks_i[rrow][c] = Ai[(size_t)(col0+rrow)*INNER + kt + c];
            }
        }
        __syncthreads();
        #pragma unroll
        for (int kk = 0; kk < 32; kk++) {
            float qr0 = Qs_r[ty][kk],    qi0 = Qs_i[ty][kk];
            float qr1 = Qs_r[ty+16][kk], qi1 = Qs_i[ty+16][kk];
            float kr0 = Ks_r[tx][kk],    ki0 = Ks_i[tx][kk];
            float kr1 = Ks_r[tx+16][kk], ki1 = Ks_i[tx+16][kk];
            ar00 += qr0*kr0 + qi0*ki0;  ai00 += qi0*kr0 - qr0*ki0;
            ar01 += qr0*kr1 + qi0*ki1;  ai01 += qi0*kr1 - qr0*ki1;
            ar10 += qr1*kr0 + qi1*ki0;  ai10 += qi1*kr0 - qr1*ki0;
            ar11 += qr1*kr1 + qi1*ki1;  ai11 += qi1*kr1 - qr1*ki1;
        }
        __syncthreads();
    }

    const float SCALE = 0.125f;
    size_t obase = (size_t)bh*SEQ*SEQ;
    float accr[2][2] = {{ar00, ar01},{ar10, ar11}};
    float acci[2][2] = {{ai00, ai01},{ai10, ai11}};
    #pragma unroll
    for (int j = 0; j < 2; j++) {
        int row = row0 + ty + 16*j;
        #pragma unroll
        for (int i = 0; i < 2; i++) {
            int col = col0 + tx + 16*i;
            g_d_re[obase + (size_t)row*SEQ + col] = accr[j][i]*SCALE;
            g_d_im[obase + (size_t)row*SEQ + col] = acci[j][i]*SCALE;
        }
    }
}

// ---------------- softmax on |d| + polar (in place) ----------------
__global__ void softmax_polar()
{
    size_t base = (size_t)blockIdx.x * SEQ;
    int t = threadIdx.x;
    float re[4], im[4], mg[4];
    float lmax = -3.4e38f;
    #pragma unroll
    for (int j = 0; j < 4; j++) {
        size_t idx = base + t + 256*j;
        re[j] = g_d_re[idx]; im[j] = g_d_im[idx];
        mg[j] = sqrtf(re[j]*re[j] + im[j]*im[j]);
        lmax = fmaxf(lmax, mg[j]);
    }
    __shared__ float sw[8];
    float v = lmax;
    #pragma unroll
    for (int o = 16; o > 0; o >>= 1) v = fmaxf(v, __shfl_xor_sync(0xffffffffu, v, o));
    if ((t & 31) == 0) sw[t>>5] = v;
    __syncthreads();
    float bmax = fmaxf(fmaxf(fmaxf(sw[0],sw[1]),fmaxf(sw[2],sw[3])),
                       fmaxf(fmaxf(sw[4],sw[5]),fmaxf(sw[6],sw[7])));
    __syncthreads();

    float e[4]; float lsum = 0.f;
    #pragma unroll
    for (int j = 0; j < 4; j++) { e[j] = __expf(mg[j] - bmax); lsum += e[j]; }
    v = lsum;
    #pragma unroll
    for (int o = 16; o > 0; o >>= 1) v += __shfl_xor_sync(0xffffffffu, v, o);
    if ((t & 31) == 0) sw[t>>5] = v;
    __syncthreads();
    float bsum = sw[0]+sw[1]+sw[2]+sw[3]+sw[4]+sw[5]+sw[6]+sw[7];
    float inv = 1.0f / bsum;

    #pragma unroll
    for (int j = 0; j < 4; j++) {
        size_t idx = base + t + 256*j;
        float amp = e[j] * inv;
        if (mg[j] > 0.f) {
            float c = amp / mg[j];
            g_d_re[idx] = re[j]*c;
            g_d_im[idx] = im[j]*c;
        } else {
            g_d_re[idx] = amp;
            g_d_im[idx] = 0.f;
        }
    }
}

// ---------------- AV: O = C @ V per (b,h) ----------------
__global__ void av_kernel()
{
    int bh = blockIdx.z; int b = bh >> 2, h = bh & 3;
    const float* Cr = g_d_re + (size_t)bh*SEQ*SEQ;
    const float* Ci = g_d_im + (size_t)bh*SEQ*SEQ;
    const float* Vr = g_w_re + (size_t)b*SEQ*INNER + h*DH;
    const float* Vi = g_w_im + (size_t)b*SEQ*INNER + h*DH;
    __shared__ float Cs_r[32][33], Cs_i[32][33], Vs_r[32][33], Vs_i[32][33];
    int tx = threadIdx.x, ty = threadIdx.y;
    int row0 = blockIdx.y*32, col0 = blockIdx.x*32;
    float ar00=0,ai00=0, ar01=0,ai01=0, ar10=0,ai10=0, ar11=0,ai11=0;

    for (int kt = 0; kt < SEQ; kt += 32) {
        #pragma unroll
        for (int j = 0; j < 2; j++) {
            int rrow = ty + 16*j;
            #pragma unroll
            for (int i = 0; i < 2; i++) {
                int c = tx + 16*i;
                Cs_r[rrow][c] = Cr[(size_t)(row0+rrow)*SEQ + kt + c];
                Cs_i[rrow][c] = Ci[(size_t)(row0+rrow)*SEQ + kt + c];
                Vs_r[rrow][c] = Vr[(size_t)(kt+rrow)*INNER + col0 + c];
                Vs_i[rrow][c] = Vi[(size_t)(kt+rrow)*INNER + col0 + c];
            }
        }
        __syncthreads();
        #pragma unroll
        for (int kk = 0; kk < 32; kk++) {
            float cr0 = Cs_r[ty][kk],    ci0 = Cs_i[ty][kk];
            float cr1 = Cs_r[ty+16][kk], ci1 = Cs_i[ty+16][kk];
            float vr0 = Vs_r[kk][tx],    vi0 = Vs_i[kk][tx];
            float vr1 = Vs_r[kk][tx+16], vi1 = Vs_i[kk][tx+16];
            ar00 += cr0*vr0 - ci0*vi0;  ai00 += cr0*vi0 + ci0*vr0;
            ar01 += cr0*vr1 - ci0*vi1;  ai01 += cr0*vi1 + ci0*vr1;
            ar10 += cr1*vr0 - ci1*vi0;  ai10 += cr1*vi0 + ci1*vr0;
            ar11 += cr1*vr1 - ci1*vi1;  ai11 += cr1*vi1 + ci1*vr1;
        }
        __syncthreads();
    }

    float accr[2][2] = {{ar00, ar01},{ar10, ar11}};
    float acci[2][2] = {{ai00, ai01},{ai10, ai11}};
    #pragma unroll
    for (int j = 0; j < 2; j++) {
        int row = row0 + ty + 16*j;
        #pragma unroll
        for (int i = 0; i < 2; i++) {
            int col = col0 + tx + 16*i;
            size_t oi = (size_t)(b*SEQ + row)*INNER + h*DH + col;
            g_att_re[oi] = accr[j][i];
            g_att_im[oi] = acci[j][i];
        }
    }
}

// ---------------- host launcher ----------------
extern "C" void kernel_launch(void* const* d_in, const int* in_sizes, int n_in,
                              void* d_out, int out_size)
{
    if (n_in < 18 || d_out == nullptr) return;

    // Group inputs by size class; insertion order within class (matches metadata order).
    int ix[2], nx = 0;    // 524288: x_re, x_im
    int iw[6], nw = 0;    // 262144: qkv_re, qkv_im, out_w_re, out_w_im, ff_re, ff_im
    int ip[10], np = 0;   // 1024:   ln1 w/b, out_b, ln2 w/b
    for (int i = 0; i < n_in; i++) {
        if      (in_sizes[i] == MTOK*DIMC        && nx < 2)  ix[nx++] = i;
        else if (in_sizes[i] == DEPTH*INNER*DIMC && nw < 6)  iw[nw++] = i;
        else if (in_sizes[i] == DEPTH*DIMC       && np < 10) ip[np++] = i;
    }
    if (nx != 2 || nw != 6 || np != 10) return;

    const float* x_re     = (const float*)d_in[ix[0]];
    const float* x_im     = (const float*)d_in[ix[1]];
    const float* qkv_re   = (const float*)d_in[iw[0]];
    const float* qkv_im   = (const float*)d_in[iw[1]];
    const float* out_w_re = (const float*)d_in[iw[2]];
    const float* out_w_im = (const float*)d_in[iw[3]];
    const float* ff_re    = (const float*)d_in[iw[4]];
    const float* ff_im    = (const float*)d_in[iw[5]];
    const float* ln1_w_re = (const float*)d_in[ip[0]];
    const float* ln1_w_im = (const float*)d_in[ip[1]];
    const float* ln1_b_re = (const float*)d_in[ip[2]];
    const float* ln1_b_im = (const float*)d_in[ip[3]];
    const float* out_b_re = (const float*)d_in[ip[4]];
    const float* out_b_im = (const float*)d_in[ip[5]];
    const float* ln2_w_re = (const float*)d_in[ip[6]];
    const float* ln2_w_im = (const float*)d_in[ip[7]];
    const float* ln2_b_re = (const float*)d_in[ip[8]];
    const float* ln2_b_im = (const float*)d_in[ip[9]];

    const int nTok = MTOK*DIMC;
    init_x_kernel<<<(nTok+255)/256, 256>>>(x_re, x_im, nTok);

    dim3 thr16(16,16);
    const int WSLICE = INNER*DIMC;
    for (int l = 0; l < DEPTH; l++) {
        ln_kernel<<<MTOK, 256>>>(0,
                                 ln1_w_re + l*DIMC, ln1_w_im + l*DIMC,
                                 ln1_b_re + l*DIMC, ln1_b_im + l*DIMC);
        gemm_xwt<0><<<dim3(INNER/32, MTOK/32), thr16>>>(
            1, qkv_re + (size_t)l*WSLICE, qkv_im + (size_t)l*WSLICE,
            2, DIMC, DIMC, DIMC, INNER, nullptr, nullptr, 0);
        dots_kernel<<<dim3(SEQ/32, SEQ/32, BATCH*HEADS), thr16>>>();
        softmax_polar<<<BATCH*HEADS*SEQ, 256>>>();
        av_kernel<<<dim3(DH/32, SEQ/32, BATCH*HEADS), thr16>>>();
        gemm_xwt<1><<<dim3(DIMC/32, MTOK/32), thr16>>>(
            3, out_w_re + (size_t)l*WSLICE, out_w_im + (size_t)l*WSLICE,
            4, INNER, INNER, INNER, DIMC,
            out_b_re + l*DIMC, out_b_im + l*DIMC, 0);
        ln_kernel<<<MTOK, 256>>>(4,
                                 ln2_w_re + l*DIMC, ln2_w_im + l*DIMC,
                                 ln2_b_re + l*DIMC, ln2_b_im + l*DIMC);
        gemm_xwt<2><<<dim3(DIMC/32, MTOK/32), thr16>>>(
            1, ff_re + (size_t)l*WSLICE, ff_im + (size_t)l*WSLICE,
            0, DIMC, DIMC, DIMC, DIMC,
            nullptr, nullptr, 1);
    }

    // Output: real part only (float32 lowering of complex64 drops imag).
    int nOut = nTok < out_size ? nTok : out_size;
    pack_out_kernel<<<(nOut+255)/256, 256>>>((float*)d_out, nOut);
}

// round 9
// speedup vs baseline: 1.1554x; 1.1554x over previous
#include <cuda_runtime.h>
#include <math.h>

#define BATCH 2
#define SEQ   1024
#define DIMC  256
#define HEADS 4
#define DH    64
#define INNER 256
#define MTOK  (BATCH*SEQ)   // 2048
#define DEPTH 4

#define ACT_CAP ((size_t)MTOK*DIMC)                 // 524288
#define SCR_CAP ((size_t)BATCH*HEADS*SEQ*SEQ)       // 8388608

// GEMM tiling: 64x64 block tile, K-slice 16, 256 threads, 4x4 complex microtile
#define BK 16
#define BPAD 68   // row stride for k-major shared tiles (64 + 4 pad, multiple of 4)

// ---------------- scratch (device globals) ----------------
__device__ float g_x_re[ACT_CAP],  g_x_im[ACT_CAP];
__device__ float g_xn_re[ACT_CAP], g_xn_im[ACT_CAP];
__device__ float g_w_re[ACT_CAP],  g_w_im[ACT_CAP];
__device__ float g_att_re[ACT_CAP],g_att_im[ACT_CAP];
__device__ float g_gx_re[ACT_CAP], g_gx_im[ACT_CAP];
__device__ float g_d_re[SCR_CAP];
__device__ float g_d_im[SCR_CAP];

__device__ __forceinline__ float* gbuf(int id, int comp) {
    switch (id) {
        case 0: return comp ? g_x_im   : g_x_re;
        case 1: return comp ? g_xn_im  : g_xn_re;
        case 2: return comp ? g_w_im   : g_w_re;
        case 3: return comp ? g_att_im : g_att_re;
        default:return comp ? g_gx_im  : g_gx_re;
    }
}

// ---------------- input copy ----------------
__global__ void init_x_kernel(const float* __restrict__ a, const float* __restrict__ b, int n)
{
    int i = blockIdx.x*blockDim.x + threadIdx.x;
    if (i < n) { g_x_re[i] = a[i]; g_x_im[i] = b[i]; }
}

// ---------------- output pack: real part only ----------------
__global__ void pack_out_kernel(float* __restrict__ out, int n)
{
    int i = blockIdx.x*blockDim.x + threadIdx.x;
    if (i < n) out[i] = g_x_re[i];
}

// ---------------- complex layernorm ----------------
__global__ void ln_kernel(int srcid,
                          const float* __restrict__ wr, const float* __restrict__ wi,
                          const float* __restrict__ br, const float* __restrict__ bi)
{
    const float* xr = gbuf(srcid, 0);
    const float* xi = gbuf(srcid, 1);
    float* yr = gbuf(1, 0);
    float* yi = gbuf(1, 1);

    int tok = blockIdx.x;
    int t   = threadIdx.x;           // 256 threads == DIMC
    size_t xidx = (size_t)tok*DIMC + t;
    float vr = xr[xidx];
    float vi = xi[xidx];

    float s0 = vr, s1 = vi, s2 = vr*vr, s3 = vi*vi;
    #pragma unroll
    for (int o = 16; o > 0; o >>= 1) {
        s0 += __shfl_xor_sync(0xffffffffu, s0, o);
        s1 += __shfl_xor_sync(0xffffffffu, s1, o);
        s2 += __shfl_xor_sync(0xffffffffu, s2, o);
        s3 += __shfl_xor_sync(0xffffffffu, s3, o);
    }
    __shared__ float sh0[8], sh1[8], sh2[8], sh3[8];
    int warp = t >> 5;
    if ((t & 31) == 0) { sh0[warp]=s0; sh1[warp]=s1; sh2[warp]=s2; sh3[warp]=s3; }
    __syncthreads();
    float t0=0.f, t1=0.f, t2=0.f, t3=0.f;
    #pragma unroll
    for (int i = 0; i < 8; i++) { t0+=sh0[i]; t1+=sh1[i]; t2+=sh2[i]; t3+=sh3[i]; }

    const float inv = 1.0f / DIMC;
    float mr = t0*inv, mi = t1*inv;
    float var_r = t2*inv - mr*mr;
    float var_i = t3*inv - mi*mi;
    float a = var_r + 1e-5f, b = var_i;
    float r = sqrtf(a*a + b*b);
    float sre = sqrtf(fmaxf(0.5f*(r + a), 0.f));
    float sim = sqrtf(fmaxf(0.5f*(r - a), 0.f));
    if (b < 0.f) sim = -sim;
    float invr = 1.0f / fmaxf(r, 1e-30f);
    float dxr = vr - mr, dxi = vi - mi;
    float xnr = (dxr*sre + dxi*sim) * invr;
    float xni = (dxi*sre - dxr*sim) * invr;
    float Wr = wr[t], Wi = wi[t];
    yr[xidx] = Wr*xnr - Wi*xni + br[t];
    yi[xidx] = Wr*xni + Wi*xnr + bi[t];
}

// Fragment load helper: 4 consecutive floats from k-major shared row
#define LOAD_FRAG(dst, arr, kk, off)  { float4 _f = *(const float4*)&arr[kk][off]; \
                                        dst[0]=_f.x; dst[1]=_f.y; dst[2]=_f.z; dst[3]=_f.w; }

// ---------------- complex GEMM: Y[M,N] = X[M,K] @ W[N,K]^T (+ epilogue) ----------------
// MODE 0: plain   MODE 1: +bias[col]+residual   MODE 2: CReLU(res + 0.1*y - 0.01_real)
template <int MODE>
__global__ __launch_bounds__(256)
void gemm_xwt(int xid,
              const float* __restrict__ Wr, const float* __restrict__ Wi,
              int yid, int K, int ldx, int ldw, int ldy,
              const float* __restrict__ br, const float* __restrict__ bi,
              int rid)
{
    const float* Xr = gbuf(xid, 0);
    const float* Xi = gbuf(xid, 1);
    float* Yr = gbuf(yid, 0);
    float* Yi = gbuf(yid, 1);

    __shared__ __align__(16) float As_r[BK][BPAD], As_i[BK][BPAD];
    __shared__ __align__(16) float Bs_r[BK][BPAD], Bs_i[BK][BPAD];

    int tid = threadIdx.x;
    int tx = tid & 15, ty = tid >> 4;
    int row0 = blockIdx.y*64, col0 = blockIdx.x*64;

    float cr[4][4] = {}, ci[4][4] = {};

    for (int kt = 0; kt < K; kt += BK) {
        #pragma unroll
        for (int i = 0; i < 4; i++) {
            int e = tid + i*256;
            int r = e >> 4, c = e & 15;   // 64 rows x 16 k-cols
            As_r[c][r] = Xr[(size_t)(row0+r)*ldx + kt + c];
            As_i[c][r] = Xi[(size_t)(row0+r)*ldx + kt + c];
            Bs_r[c][r] = Wr[(size_t)(col0+r)*ldw + kt + c];
            Bs_i[c][r] = Wi[(size_t)(col0+r)*ldw + kt + c];
        }
        __syncthreads();
        #pragma unroll
        for (int kk = 0; kk < BK; kk++) {
            float ar[4], ai2[4], br4[4], bi4[4];
            LOAD_FRAG(ar,  As_r, kk, ty*4);
            LOAD_FRAG(ai2, As_i, kk, ty*4);
            LOAD_FRAG(br4, Bs_r, kk, tx*4);
            LOAD_FRAG(bi4, Bs_i, kk, tx*4);
            #pragma unroll
            for (int i = 0; i < 4; i++)
                #pragma unroll
                for (int j = 0; j < 4; j++) {
                    cr[i][j] += ar[i]*br4[j] - ai2[i]*bi4[j];
                    ci[i][j] += ar[i]*bi4[j] + ai2[i]*br4[j];
                }
        }
        __syncthreads();
    }

    const float* rr = gbuf(rid, 0);
    const float* ri = gbuf(rid, 1);
    int colb = col0 + tx*4;
    #pragma unroll
    for (int i = 0; i < 4; i++) {
        int row = row0 + ty*4 + i;
        size_t oi = (size_t)row*ldy + colb;
        float4 yr4, yi4;
        if (MODE == 0) {
            yr4 = make_float4(cr[i][0], cr[i][1], cr[i][2], cr[i][3]);
            yi4 = make_float4(ci[i][0], ci[i][1], ci[i][2], ci[i][3]);
        } else if (MODE == 1) {
            float4 b_r = *(const float4*)&br[colb];
            float4 b_i = *(const float4*)&bi[colb];
            float4 r_r = *(const float4*)&rr[oi];
            float4 r_i = *(const float4*)&ri[oi];
            yr4 = make_float4(cr[i][0]+b_r.x+r_r.x, cr[i][1]+b_r.y+r_r.y,
                              cr[i][2]+b_r.z+r_r.z, cr[i][3]+b_r.w+r_r.w);
            yi4 = make_float4(ci[i][0]+b_i.x+r_i.x, ci[i][1]+b_i.y+r_i.y,
                              ci[i][2]+b_i.z+r_i.z, ci[i][3]+b_i.w+r_i.w);
        } else {
            float4 r_r = *(const float4*)&rr[oi];
            float4 r_i = *(const float4*)&ri[oi];
            yr4 = make_float4(fmaxf(r_r.x + 0.1f*cr[i][0] - 0.01f, 0.f),
                              fmaxf(r_r.y + 0.1f*cr[i][1] - 0.01f, 0.f),
                              fmaxf(r_r.z + 0.1f*cr[i][2] - 0.01f, 0.f),
                              fmaxf(r_r.w + 0.1f*cr[i][3] - 0.01f, 0.f));
            yi4 = make_float4(fmaxf(r_i.x + 0.1f*ci[i][0], 0.f),
                              fmaxf(r_i.y + 0.1f*ci[i][1], 0.f),
                              fmaxf(r_i.z + 0.1f*ci[i][2], 0.f),
                              fmaxf(r_i.w + 0.1f*ci[i][3], 0.f));
        }
        *(float4*)&Yr[oi] = yr4;
        *(float4*)&Yi[oi] = yi4;
    }
}

// ---------------- dots: D[row,col] = 0.125 * sum_k Q[row,k] * conj(Q[col,k]) per bh ----------------
__global__ __launch_bounds__(256)
void dots_kernel()
{
    int bh = blockIdx.z;
    int b = bh >> 2, h = bh & 3;
    const float* Ar = g_w_re + (size_t)b*SEQ*INNER + h*DH;
    const float* Ai = g_w_im + (size_t)b*SEQ*INNER + h*DH;

    __shared__ __align__(16) float As_r[BK][BPAD], As_i[BK][BPAD];
    __shared__ __align__(16) float Bs_r[BK][BPAD], Bs_i[BK][BPAD];

    int tid = threadIdx.x;
    int tx = tid & 15, ty = tid >> 4;
    int row0 = blockIdx.y*64, col0 = blockIdx.x*64;

    float cr[4][4] = {}, ci[4][4] = {};

    #pragma unroll
    for (int kt = 0; kt < DH; kt += BK) {
        #pragma unroll
        for (int i = 0; i < 4; i++) {
            int e = tid + i*256;
            int r = e >> 4, c = e & 15;
            As_r[c][r] = Ar[(size_t)(row0+r)*INNER + kt + c];
            As_i[c][r] = Ai[(size_t)(row0+r)*INNER + kt + c];
            Bs_r[c][r] = Ar[(size_t)(col0+r)*INNER + kt + c];
            Bs_i[c][r] = Ai[(size_t)(col0+r)*INNER + kt + c];
        }
        __syncthreads();
        #pragma unroll
        for (int kk = 0; kk < BK; kk++) {
            float ar[4], ai2[4], br4[4], bi4[4];
            LOAD_FRAG(ar,  As_r, kk, ty*4);
            LOAD_FRAG(ai2, As_i, kk, ty*4);
            LOAD_FRAG(br4, Bs_r, kk, tx*4);
            LOAD_FRAG(bi4, Bs_i, kk, tx*4);
            #pragma unroll
            for (int i = 0; i < 4; i++)
                #pragma unroll
                for (int j = 0; j < 4; j++) {
                    // q * conj(k)
                    cr[i][j] += ar[i]*br4[j] + ai2[i]*bi4[j];
                    ci[i][j] += ai2[i]*br4[j] - ar[i]*bi4[j];
                }
        }
        __syncthreads();
    }

    const float SCALE = 0.125f;
    size_t obase = (size_t)bh*SEQ*SEQ;
    int colb = col0 + tx*4;
    #pragma unroll
    for (int i = 0; i < 4; i++) {
        int row = row0 + ty*4 + i;
        size_t oi = obase + (size_t)row*SEQ + colb;
        *(float4*)&g_d_re[oi] = make_float4(cr[i][0]*SCALE, cr[i][1]*SCALE,
                                            cr[i][2]*SCALE, cr[i][3]*SCALE);
        *(float4*)&g_d_im[oi] = make_float4(ci[i][0]*SCALE, ci[i][1]*SCALE,
                                            ci[i][2]*SCALE, ci[i][3]*SCALE);
    }
}

// ---------------- softmax on |d| + polar (in place) ----------------
__global__ void softmax_polar()
{
    size_t base = (size_t)blockIdx.x * SEQ;
    int t = threadIdx.x;
    float re[4], im[4], mg[4];
    float lmax = -3.4e38f;
    #pragma unroll
    for (int j = 0; j < 4; j++) {
        size_t idx = base + t + 256*j;
        re[j] = g_d_re[idx]; im[j] = g_d_im[idx];
        mg[j] = sqrtf(re[j]*re[j] + im[j]*im[j]);
        lmax = fmaxf(lmax, mg[j]);
    }
    __shared__ float sw[8];
    float v = lmax;
    #pragma unroll
    for (int o = 16; o > 0; o >>= 1) v = fmaxf(v, __shfl_xor_sync(0xffffffffu, v, o));
    if ((t & 31) == 0) sw[t>>5] = v;
    __syncthreads();
    float bmax = fmaxf(fmaxf(fmaxf(sw[0],sw[1]),fmaxf(sw[2],sw[3])),
                       fmaxf(fmaxf(sw[4],sw[5]),fmaxf(sw[6],sw[7])));
    __syncthreads();

    float e[4]; float lsum = 0.f;
    #pragma unroll
    for (int j = 0; j < 4; j++) { e[j] = __expf(mg[j] - bmax); lsum += e[j]; }
    v = lsum;
    #pragma unroll
    for (int o = 16; o > 0; o >>= 1) v += __shfl_xor_sync(0xffffffffu, v, o);
    if ((t & 31) == 0) sw[t>>5] = v;
    __syncthreads();
    float bsum = sw[0]+sw[1]+sw[2]+sw[3]+sw[4]+sw[5]+sw[6]+sw[7];
    float inv = 1.0f / bsum;

    #pragma unroll
    for (int j = 0; j < 4; j++) {
        size_t idx = base + t + 256*j;
        float amp = e[j] * inv;
        if (mg[j] > 0.f) {
            float c = amp / mg[j];
            g_d_re[idx] = re[j]*c;
            g_d_im[idx] = im[j]*c;
        } else {
            g_d_re[idx] = amp;
            g_d_im[idx] = 0.f;
        }
    }
}

// ---------------- AV: O[row, d] = sum_m C[row,m] * V[m,d] per bh ----------------
__global__ __launch_bounds__(256)
void av_kernel()
{
    int bh = blockIdx.y; int b = bh >> 2, h = bh & 3;
    const float* Cr = g_d_re + (size_t)bh*SEQ*SEQ;
    const float* Ci = g_d_im + (size_t)bh*SEQ*SEQ;
    const float* Vr = g_w_re + (size_t)b*SEQ*INNER + h*DH;
    const float* Vi = g_w_im + (size_t)b*SEQ*INNER + h*DH;

    __shared__ __align__(16) float As_r[BK][BPAD], As_i[BK][BPAD];
    __shared__ __align__(16) float Bs_r[BK][BPAD], Bs_i[BK][BPAD];

    int tid = threadIdx.x;
    int tx = tid & 15, ty = tid >> 4;
    int row0 = blockIdx.x*64;     // N-dim (DH=64) covered by one tile

    float cr[4][4] = {}, ci[4][4] = {};

    for (int kt = 0; kt < SEQ; kt += BK) {
        #pragma unroll
        for (int i = 0; i < 4; i++) {
            int e = tid + i*256;
            { // A tile (scores), k-major transpose store
                int r = e >> 4, c = e & 15;
                As_r[c][r] = Cr[(size_t)(row0+r)*SEQ + kt + c];
                As_i[c][r] = Ci[(size_t)(row0+r)*SEQ + kt + c];
            }
            { // B tile (V), rows = k, cols = DH, direct store
                int r = e >> 6, c = e & 63;
                Bs_r[r][c] = Vr[(size_t)(kt+r)*INNER + c];
                Bs_i[r][c] = Vi[(size_t)(kt+r)*INNER + c];
            }
        }
        __syncthreads();
        #pragma unroll
        for (int kk = 0; kk < BK; kk++) {
            float ar[4], ai2[4], br4[4], bi4[4];
            LOAD_FRAG(ar,  As_r, kk, ty*4);
            LOAD_FRAG(ai2, As_i, kk, ty*4);
            LOAD_FRAG(br4, Bs_r, kk, tx*4);
            LOAD_FRAG(bi4, Bs_i, kk, tx*4);
            #pragma unroll
            for (int i = 0; i < 4; i++)
                #pragma unroll
                for (int j = 0; j < 4; j++) {
                    cr[i][j] += ar[i]*br4[j] - ai2[i]*bi4[j];
                    ci[i][j] += ar[i]*bi4[j] + ai2[i]*br4[j];
                }
        }
        __syncthreads();
    }

    int colb = h*DH + tx*4;
    #pragma unroll
    for (int i = 0; i < 4; i++) {
        int row = row0 + ty*4 + i;
        size_t oi = (size_t)(b*SEQ + row)*INNER + colb;
        *(float4*)&g_att_re[oi] = make_float4(cr[i][0], cr[i][1], cr[i][2], cr[i][3]);
        *(float4*)&g_att_im[oi] = make_float4(ci[i][0], ci[i][1], ci[i][2], ci[i][3]);
    }
}

// ---------------- host launcher ----------------
extern "C" void kernel_launch(void* const* d_in, const int* in_sizes, int n_in,
                              void* d_out, int out_size)
{
    if (n_in < 18 || d_out == nullptr) return;

    int ix[2], nx = 0;
    int iw[6], nw = 0;
    int ip[10], np = 0;
    for (int i = 0; i < n_in; i++) {
        if      (in_sizes[i] == MTOK*DIMC        && nx < 2)  ix[nx++] = i;
        else if (in_sizes[i] == DEPTH*INNER*DIMC && nw < 6)  iw[nw++] = i;
        else if (in_sizes[i] == DEPTH*DIMC       && np < 10) ip[np++] = i;
    }
    if (nx != 2 || nw != 6 || np != 10) return;

    const float* x_re     = (const float*)d_in[ix[0]];
    const float* x_im     = (const float*)d_in[ix[1]];
    const float* qkv_re   = (const float*)d_in[iw[0]];
    const float* qkv_im   = (const float*)d_in[iw[1]];
    const float* out_w_re = (const float*)d_in[iw[2]];
    const float* out_w_im = (const float*)d_in[iw[3]];
    const float* ff_re    = (const float*)d_in[iw[4]];
    const float* ff_im    = (const float*)d_in[iw[5]];
    const float* ln1_w_re = (const float*)d_in[ip[0]];
    const float* ln1_w_im = (const float*)d_in[ip[1]];
    const float* ln1_b_re = (const float*)d_in[ip[2]];
    const float* ln1_b_im = (const float*)d_in[ip[3]];
    const float* out_b_re = (const float*)d_in[ip[4]];
    const float* out_b_im = (const float*)d_in[ip[5]];
    const float* ln2_w_re = (const float*)d_in[ip[6]];
    const float* ln2_w_im = (const float*)d_in[ip[7]];
    const float* ln2_b_re = (const float*)d_in[ip[8]];
    const float* ln2_b_im = (const float*)d_in[ip[9]];

    const int nTok = MTOK*DIMC;
    init_x_kernel<<<(nTok+255)/256, 256>>>(x_re, x_im, nTok);

    const int WSLICE = INNER*DIMC;
    for (int l = 0; l < DEPTH; l++) {
        ln_kernel<<<MTOK, 256>>>(0,
                                 ln1_w_re + l*DIMC, ln1_w_im + l*DIMC,
                                 ln1_b_re + l*DIMC, ln1_b_im + l*DIMC);
        gemm_xwt<0><<<dim3(INNER/64, MTOK/64), 256>>>(
            1, qkv_re + (size_t)l*WSLICE, qkv_im + (size_t)l*WSLICE,
            2, DIMC, DIMC, DIMC, INNER, nullptr, nullptr, 0);
        dots_kernel<<<dim3(SEQ/64, SEQ/64, BATCH*HEADS), 256>>>();
        softmax_polar<<<BATCH*HEADS*SEQ, 256>>>();
        av_kernel<<<dim3(SEQ/64, BATCH*HEADS), 256>>>();
        gemm_xwt<1><<<dim3(DIMC/64, MTOK/64), 256>>>(
            3, out_w_re + (size_t)l*WSLICE, out_w_im + (size_t)l*WSLICE,
            4, INNER, INNER, INNER, DIMC,
            out_b_re + l*DIMC, out_b_im + l*DIMC, 0);
        ln_kernel<<<MTOK, 256>>>(4,
                                 ln2_w_re + l*DIMC, ln2_w_im + l*DIMC,
                                 ln2_b_re + l*DIMC, ln2_b_im + l*DIMC);
        gemm_xwt<2><<<dim3(DIMC/64, MTOK/64), 256>>>(
            1, ff_re + (size_t)l*WSLICE, ff_im + (size_t)l*WSLICE,
            0, DIMC, DIMC, DIMC, DIMC,
            nullptr, nullptr, 1);
    }

    int nOut = nTok < out_size ? nTok : out_size;
    pack_out_kernel<<<(nOut+255)/256, 256>>>((float*)d_out, nOut);
}

// round 10
// speedup vs baseline: 1.2187x; 1.0548x over previous
#include <cuda_runtime.h>
#include <math.h>

#define BATCH 2
#define SEQ   1024
#define DIMC  256
#define HEADS 4
#define DH    64
#define INNER 256
#define MTOK  (BATCH*SEQ)   // 2048
#define DEPTH 4

#define ACT_CAP ((size_t)MTOK*DIMC)                 // 524288
#define SCR_CAP ((size_t)BATCH*HEADS*SEQ*SEQ)       // 8388608

#define BK 16
#define BPAD 68   // 64 + 4 pad, multiple of 4 for float4 alignment

// ---------------- scratch (device globals) ----------------
__device__ float g_x_re[ACT_CAP],  g_x_im[ACT_CAP];
__device__ float g_xn_re[ACT_CAP], g_xn_im[ACT_CAP];
__device__ float g_w_re[ACT_CAP],  g_w_im[ACT_CAP];
__device__ float g_att_re[ACT_CAP],g_att_im[ACT_CAP];
__device__ float g_gx_re[ACT_CAP], g_gx_im[ACT_CAP];
__device__ float g_d_re[SCR_CAP];
__device__ float g_d_im[SCR_CAP];

__device__ __forceinline__ float* gbuf(int id, int comp) {
    switch (id) {
        case 0: return comp ? g_x_im   : g_x_re;
        case 1: return comp ? g_xn_im  : g_xn_re;
        case 2: return comp ? g_w_im   : g_w_re;
        case 3: return comp ? g_att_im : g_att_re;
        default:return comp ? g_gx_im  : g_gx_re;
    }
}

// ---------------- input copy ----------------
__global__ void init_x_kernel(const float* __restrict__ a, const float* __restrict__ b, int n)
{
    int i = blockIdx.x*blockDim.x + threadIdx.x;
    if (i < n) { g_x_re[i] = a[i]; g_x_im[i] = b[i]; }
}

// ---------------- output pack: real part only ----------------
__global__ void pack_out_kernel(float* __restrict__ out, int n)
{
    int i = blockIdx.x*blockDim.x + threadIdx.x;
    if (i < n) out[i] = g_x_re[i];
}

// ---------------- complex layernorm ----------------
__global__ void ln_kernel(int srcid,
                          const float* __restrict__ wr, const float* __restrict__ wi,
                          const float* __restrict__ br, const float* __restrict__ bi)
{
    const float* xr = gbuf(srcid, 0);
    const float* xi = gbuf(srcid, 1);
    float* yr = gbuf(1, 0);
    float* yi = gbuf(1, 1);

    int tok = blockIdx.x;
    int t   = threadIdx.x;           // 256 threads == DIMC
    size_t xidx = (size_t)tok*DIMC + t;
    float vr = xr[xidx];
    float vi = xi[xidx];

    float s0 = vr, s1 = vi, s2 = vr*vr, s3 = vi*vi;
    #pragma unroll
    for (int o = 16; o > 0; o >>= 1) {
        s0 += __shfl_xor_sync(0xffffffffu, s0, o);
        s1 += __shfl_xor_sync(0xffffffffu, s1, o);
        s2 += __shfl_xor_sync(0xffffffffu, s2, o);
        s3 += __shfl_xor_sync(0xffffffffu, s3, o);
    }
    __shared__ float sh0[8], sh1[8], sh2[8], sh3[8];
    int warp = t >> 5;
    if ((t & 31) == 0) { sh0[warp]=s0; sh1[warp]=s1; sh2[warp]=s2; sh3[warp]=s3; }
    __syncthreads();
    float t0=0.f, t1=0.f, t2=0.f, t3=0.f;
    #pragma unroll
    for (int i = 0; i < 8; i++) { t0+=sh0[i]; t1+=sh1[i]; t2+=sh2[i]; t3+=sh3[i]; }

    const float inv = 1.0f / DIMC;
    float mr = t0*inv, mi = t1*inv;
    float var_r = t2*inv - mr*mr;
    float var_i = t3*inv - mi*mi;
    float a = var_r + 1e-5f, b = var_i;
    float r = sqrtf(a*a + b*b);
    float sre = sqrtf(fmaxf(0.5f*(r + a), 0.f));
    float sim = sqrtf(fmaxf(0.5f*(r - a), 0.f));
    if (b < 0.f) sim = -sim;
    float invr = 1.0f / fmaxf(r, 1e-30f);
    float dxr = vr - mr, dxi = vi - mi;
    float xnr = (dxr*sre + dxi*sim) * invr;
    float xni = (dxi*sre - dxr*sim) * invr;
    float Wr = wr[t], Wi = wi[t];
    yr[xidx] = Wr*xnr - Wi*xni + br[t];
    yi[xidx] = Wr*xni + Wi*xnr + bi[t];
}

#define LOAD_FRAG(dst, arr, kk, off)  { float4 _f = *(const float4*)&arr[kk][off]; \
                                        dst[0]=_f.x; dst[1]=_f.y; dst[2]=_f.z; dst[3]=_f.w; }

// ---------------- complex GEMM: Y[M,N] = X[M,K] @ W[N,K]^T (+ epilogue) ----------------
template <int MODE>
__global__ __launch_bounds__(256, 2)
void gemm_xwt(int xid,
              const float* __restrict__ Wr, const float* __restrict__ Wi,
              int yid, int K, int ldx, int ldw, int ldy,
              const float* __restrict__ br, const float* __restrict__ bi,
              int rid)
{
    const float* Xr = gbuf(xid, 0);
    const float* Xi = gbuf(xid, 1);
    float* Yr = gbuf(yid, 0);
    float* Yi = gbuf(yid, 1);

    __shared__ __align__(16) float As_r[BK][BPAD], As_i[BK][BPAD];
    __shared__ __align__(16) float Bs_r[BK][BPAD], Bs_i[BK][BPAD];

    int tid = threadIdx.x;
    int tx = tid & 15, ty = tid >> 4;
    int row0 = blockIdx.y*64, col0 = blockIdx.x*64;

    float cr[4][4] = {}, ci[4][4] = {};

    for (int kt = 0; kt < K; kt += BK) {
        #pragma unroll
        for (int i = 0; i < 4; i++) {
            int e = tid + i*256;
            int r = e >> 4, c = e & 15;
            As_r[c][r] = Xr[(size_t)(row0+r)*ldx + kt + c];
            As_i[c][r] = Xi[(size_t)(row0+r)*ldx + kt + c];
            Bs_r[c][r] = Wr[(size_t)(col0+r)*ldw + kt + c];
            Bs_i[c][r] = Wi[(size_t)(col0+r)*ldw + kt + c];
        }
        __syncthreads();
        #pragma unroll
        for (int kk = 0; kk < BK; kk++) {
            float ar[4], ai2[4], br4[4], bi4[4];
            LOAD_FRAG(ar,  As_r, kk, ty*4);
            LOAD_FRAG(ai2, As_i, kk, ty*4);
            LOAD_FRAG(br4, Bs_r, kk, tx*4);
            LOAD_FRAG(bi4, Bs_i, kk, tx*4);
            #pragma unroll
            for (int i = 0; i < 4; i++)
                #pragma unroll
                for (int j = 0; j < 4; j++) {
                    cr[i][j] += ar[i]*br4[j] - ai2[i]*bi4[j];
                    ci[i][j] += ar[i]*bi4[j] + ai2[i]*br4[j];
                }
        }
        __syncthreads();
    }

    const float* rr = gbuf(rid, 0);
    const float* ri = gbuf(rid, 1);
    int colb = col0 + tx*4;
    #pragma unroll
    for (int i = 0; i < 4; i++) {
        int row = row0 + ty*4 + i;
        size_t oi = (size_t)row*ldy + colb;
        float4 yr4, yi4;
        if (MODE == 0) {
            yr4 = make_float4(cr[i][0], cr[i][1], cr[i][2], cr[i][3]);
            yi4 = make_float4(ci[i][0], ci[i][1], ci[i][2], ci[i][3]);
        } else if (MODE == 1) {
            float4 b_r = *(const float4*)&br[colb];
            float4 b_i = *(const float4*)&bi[colb];
            float4 r_r = *(const float4*)&rr[oi];
            float4 r_i = *(const float4*)&ri[oi];
            yr4 = make_float4(cr[i][0]+b_r.x+r_r.x, cr[i][1]+b_r.y+r_r.y,
                              cr[i][2]+b_r.z+r_r.z, cr[i][3]+b_r.w+r_r.w);
            yi4 = make_float4(ci[i][0]+b_i.x+r_i.x, ci[i][1]+b_i.y+r_i.y,
                              ci[i][2]+b_i.z+r_i.z, ci[i][3]+b_i.w+r_i.w);
        } else {
            float4 r_r = *(const float4*)&rr[oi];
            float4 r_i = *(const float4*)&ri[oi];
            yr4 = make_float4(fmaxf(r_r.x + 0.1f*cr[i][0] - 0.01f, 0.f),
                              fmaxf(r_r.y + 0.1f*cr[i][1] - 0.01f, 0.f),
                              fmaxf(r_r.z + 0.1f*cr[i][2] - 0.01f, 0.f),
                              fmaxf(r_r.w + 0.1f*cr[i][3] - 0.01f, 0.f));
            yi4 = make_float4(fmaxf(r_i.x + 0.1f*ci[i][0], 0.f),
                              fmaxf(r_i.y + 0.1f*ci[i][1], 0.f),
                              fmaxf(r_i.z + 0.1f*ci[i][2], 0.f),
                              fmaxf(r_i.w + 0.1f*ci[i][3], 0.f));
        }
        *(float4*)&Yr[oi] = yr4;
        *(float4*)&Yi[oi] = yi4;
    }
}

// ---------------- dots: D[row,col] = 0.125 * sum_k Q[row,k] * conj(Q[col,k]) per bh ----------------
__global__ __launch_bounds__(256, 2)
void dots_kernel()
{
    int bh = blockIdx.z;
    int b = bh >> 2, h = bh & 3;
    const float* Ar = g_w_re + (size_t)b*SEQ*INNER + h*DH;
    const float* Ai = g_w_im + (size_t)b*SEQ*INNER + h*DH;

    __shared__ __align__(16) float As_r[BK][BPAD], As_i[BK][BPAD];
    __shared__ __align__(16) float Bs_r[BK][BPAD], Bs_i[BK][BPAD];

    int tid = threadIdx.x;
    int tx = tid & 15, ty = tid >> 4;
    int row0 = blockIdx.y*64, col0 = blockIdx.x*64;

    float cr[4][4] = {}, ci[4][4] = {};

    #pragma unroll
    for (int kt = 0; kt < DH; kt += BK) {
        #pragma unroll
        for (int i = 0; i < 4; i++) {
            int e = tid + i*256;
            int r = e >> 4, c = e & 15;
            As_r[c][r] = Ar[(size_t)(row0+r)*INNER + kt + c];
            As_i[c][r] = Ai[(size_t)(row0+r)*INNER + kt + c];
            Bs_r[c][r] = Ar[(size_t)(col0+r)*INNER + kt + c];
            Bs_i[c][r] = Ai[(size_t)(col0+r)*INNER + kt + c];
        }
        __syncthreads();
        #pragma unroll
        for (int kk = 0; kk < BK; kk++) {
            float ar[4], ai2[4], br4[4], bi4[4];
            LOAD_FRAG(ar,  As_r, kk, ty*4);
            LOAD_FRAG(ai2, As_i, kk, ty*4);
            LOAD_FRAG(br4, Bs_r, kk, tx*4);
            LOAD_FRAG(bi4, Bs_i, kk, tx*4);
            #pragma unroll
            for (int i = 0; i < 4; i++)
                #pragma unroll
                for (int j = 0; j < 4; j++) {
                    cr[i][j] += ar[i]*br4[j] + ai2[i]*bi4[j];
                    ci[i][j] += ai2[i]*br4[j] - ar[i]*bi4[j];
                }
        }
        __syncthreads();
    }

    const float SCALE = 0.125f;
    size_t obase = (size_t)bh*SEQ*SEQ;
    int colb = col0 + tx*4;
    #pragma unroll
    for (int i = 0; i < 4; i++) {
        int row = row0 + ty*4 + i;
        size_t oi = obase + (size_t)row*SEQ + colb;
        *(float4*)&g_d_re[oi] = make_float4(cr[i][0]*SCALE, cr[i][1]*SCALE,
                                            cr[i][2]*SCALE, cr[i][3]*SCALE);
        *(float4*)&g_d_im[oi] = make_float4(ci[i][0]*SCALE, ci[i][1]*SCALE,
                                            ci[i][2]*SCALE, ci[i][3]*SCALE);
    }
}

// ---------------- softmax on |d| + polar (in place) ----------------
__global__ void softmax_polar()
{
    size_t base = (size_t)blockIdx.x * SEQ;
    int t = threadIdx.x;
    float re[4], im[4], mg[4];
    float lmax = -3.4e38f;
    #pragma unroll
    for (int j = 0; j < 4; j++) {
        size_t idx = base + t + 256*j;
        re[j] = g_d_re[idx]; im[j] = g_d_im[idx];
        mg[j] = sqrtf(re[j]*re[j] + im[j]*im[j]);
        lmax = fmaxf(lmax, mg[j]);
    }
    __shared__ float sw[8];
    float v = lmax;
    #pragma unroll
    for (int o = 16; o > 0; o >>= 1) v = fmaxf(v, __shfl_xor_sync(0xffffffffu, v, o));
    if ((t & 31) == 0) sw[t>>5] = v;
    __syncthreads();
    float bmax = fmaxf(fmaxf(fmaxf(sw[0],sw[1]),fmaxf(sw[2],sw[3])),
                       fmaxf(fmaxf(sw[4],sw[5]),fmaxf(sw[6],sw[7])));
    __syncthreads();

    float e[4]; float lsum = 0.f;
    #pragma unroll
    for (int j = 0; j < 4; j++) { e[j] = __expf(mg[j] - bmax); lsum += e[j]; }
    v = lsum;
    #pragma unroll
    for (int o = 16; o > 0; o >>= 1) v += __shfl_xor_sync(0xffffffffu, v, o);
    if ((t & 31) == 0) sw[t>>5] = v;
    __syncthreads();
    float bsum = sw[0]+sw[1]+sw[2]+sw[3]+sw[4]+sw[5]+sw[6]+sw[7];
    float inv = 1.0f / bsum;

    #pragma unroll
    for (int j = 0; j < 4; j++) {
        size_t idx = base + t + 256*j;
        float amp = e[j] * inv;
        if (mg[j] > 0.f) {
            float c = amp / mg[j];
            g_d_re[idx] = re[j]*c;
            g_d_im[idx] = im[j]*c;
        } else {
            g_d_re[idx] = amp;
            g_d_im[idx] = 0.f;
        }
    }
}

// ---------------- AV: O[row, d] = sum_m C[row,m] * V[m,d] per bh ----------------
// 32x64 tile, 2x4 microtile, grid (32 row-tiles, 8 bh) = 256 blocks
__global__ __launch_bounds__(256, 2)
void av_kernel()
{
    int bh = blockIdx.y; int b = bh >> 2, h = bh & 3;
    const float* Cr = g_d_re + (size_t)bh*SEQ*SEQ;
    const float* Ci = g_d_im + (size_t)bh*SEQ*SEQ;
    const float* Vr = g_w_re + (size_t)b*SEQ*INNER + h*DH;
    const float* Vi = g_w_im + (size_t)b*SEQ*INNER + h*DH;

    __shared__ __align__(16) float As_r[BK][36], As_i[BK][36];   // k-major, 32 rows
    __shared__ __align__(16) float Bs_r[BK][BPAD], Bs_i[BK][BPAD]; // k rows x 64 cols

    int tid = threadIdx.x;
    int tx = tid & 15, ty = tid >> 4;
    int row0 = blockIdx.x*32;

    float cr[2][4] = {}, ci[2][4] = {};

    for (int kt = 0; kt < SEQ; kt += BK) {
        // A tile: 32 rows x 16 k (scores), transposed to k-major
        #pragma unroll
        for (int i = 0; i < 2; i++) {
            int e = tid + i*256;
            int r = e >> 4, c = e & 15;
            As_r[c][r] = Cr[(size_t)(row0+r)*SEQ + kt + c];
            As_i[c][r] = Ci[(size_t)(row0+r)*SEQ + kt + c];
        }
        // B tile: 16 k-rows x 64 cols (V), direct
        #pragma unroll
        for (int i = 0; i < 4; i++) {
            int e = tid + i*256;
            int r = e >> 6, c = e & 63;
            Bs_r[r][c] = Vr[(size_t)(kt+r)*INNER + c];
            Bs_i[r][c] = Vi[(size_t)(kt+r)*INNER + c];
        }
        __syncthreads();
        #pragma unroll
        for (int kk = 0; kk < BK; kk++) {
            float2 arf = *(const float2*)&As_r[kk][ty*2];
            float2 aif = *(const float2*)&As_i[kk][ty*2];
            float br4[4], bi4[4];
            LOAD_FRAG(br4, Bs_r, kk, tx*4);
            LOAD_FRAG(bi4, Bs_i, kk, tx*4);
            float ar[2]  = {arf.x, arf.y};
            float ai2[2] = {aif.x, aif.y};
            #pragma unroll
            for (int i = 0; i < 2; i++)
                #pragma unroll
                for (int j = 0; j < 4; j++) {
                    cr[i][j] += ar[i]*br4[j] - ai2[i]*bi4[j];
                    ci[i][j] += ar[i]*bi4[j] + ai2[i]*br4[j];
                }
        }
        __syncthreads();
    }

    int colb = h*DH + tx*4;
    #pragma unroll
    for (int i = 0; i < 2; i++) {
        int row = row0 + ty*2 + i;
        size_t oi = (size_t)(b*SEQ + row)*INNER + colb;
        *(float4*)&g_att_re[oi] = make_float4(cr[i][0], cr[i][1], cr[i][2], cr[i][3]);
        *(float4*)&g_att_im[oi] = make_float4(ci[i][0], ci[i][1], ci[i][2], ci[i][3]);
    }
}

// ---------------- host launcher ----------------
extern "C" void kernel_launch(void* const* d_in, const int* in_sizes, int n_in,
                              void* d_out, int out_size)
{
    if (n_in < 18 || d_out == nullptr) return;

    int ix[2], nx = 0;
    int iw[6], nw = 0;
    int ip[10], np = 0;
    for (int i = 0; i < n_in; i++) {
        if      (in_sizes[i] == MTOK*DIMC        && nx < 2)  ix[nx++] = i;
        else if (in_sizes[i] == DEPTH*INNER*DIMC && nw < 6)  iw[nw++] = i;
        else if (in_sizes[i] == DEPTH*DIMC       && np < 10) ip[np++] = i;
    }
    if (nx != 2 || nw != 6 || np != 10) return;

    const float* x_re     = (const float*)d_in[ix[0]];
    const float* x_im     = (const float*)d_in[ix[1]];
    const float* qkv_re   = (const float*)d_in[iw[0]];
    const float* qkv_im   = (const float*)d_in[iw[1]];
    const float* out_w_re = (const float*)d_in[iw[2]];
    const float* out_w_im = (const float*)d_in[iw[3]];
    const float* ff_re    = (const float*)d_in[iw[4]];
    const float* ff_im    = (const float*)d_in[iw[5]];
    const float* ln1_w_re = (const float*)d_in[ip[0]];
    const float* ln1_w_im = (const float*)d_in[ip[1]];
    const float* ln1_b_re = (const float*)d_in[ip[2]];
    const float* ln1_b_im = (const float*)d_in[ip[3]];
    const float* out_b_re = (const float*)d_in[ip[4]];
    const float* out_b_im = (const float*)d_in[ip[5]];
    const float* ln2_w_re = (const float*)d_in[ip[6]];
    const float* ln2_w_im = (const float*)d_in[ip[7]];
    const float* ln2_b_re = (const float*)d_in[ip[8]];
    const float* ln2_b_im = (const float*)d_in[ip[9]];

    const int nTok = MTOK*DIMC;
    init_x_kernel<<<(nTok+255)/256, 256>>>(x_re, x_im, nTok);

    const int WSLICE = INNER*DIMC;
    for (int l = 0; l < DEPTH; l++) {
        ln_kernel<<<MTOK, 256>>>(0,
                                 ln1_w_re + l*DIMC, ln1_w_im + l*DIMC,
                                 ln1_b_re + l*DIMC, ln1_b_im + l*DIMC);
        gemm_xwt<0><<<dim3(INNER/64, MTOK/64), 256>>>(
            1, qkv_re + (size_t)l*WSLICE, qkv_im + (size_t)l*WSLICE,
            2, DIMC, DIMC, DIMC, INNER, nullptr, nullptr, 0);
        dots_kernel<<<dim3(SEQ/64, SEQ/64, BATCH*HEADS), 256>>>();
        softmax_polar<<<BATCH*HEADS*SEQ, 256>>>();
        av_kernel<<<dim3(SEQ/32, BATCH*HEADS), 256>>>();
        gemm_xwt<1><<<dim3(DIMC/64, MTOK/64), 256>>>(
            3, out_w_re + (size_t)l*WSLICE, out_w_im + (size_t)l*WSLICE,
            4, INNER, INNER, INNER, DIMC,
            out_b_re + l*DIMC, out_b_im + l*DIMC, 0);
        ln_kernel<<<MTOK, 256>>>(4,
                                 ln2_w_re + l*DIMC, ln2_w_im + l*DIMC,
                                 ln2_b_re + l*DIMC, ln2_b_im + l*DIMC);
        gemm_xwt<2><<<dim3(DIMC/64, MTOK/64), 256>>>(
            1, ff_re + (size_t)l*WSLICE, ff_im + (size_t)l*WSLICE,
            0, DIMC, DIMC, DIMC, DIMC,
            nullptr, nullptr, 1);
    }

    int nOut = nTok < out_size ? nTok : out_size;
    pack_out_kernel<<<(nOut+255)/256, 256>>>((float*)d_out, nOut);
}